// round 6
// baseline (speedup 1.0000x reference)
#include <cuda_runtime.h>
#include <math.h>

#define DEPTH   6
#define D_MODEL 512
#define N_HEADS 8
#define D_HEAD  64
#define D_FF    2048
#define SEQ_T   2048
#define VOCAB   256
#define BB      2
#define MROWS   (BB * SEQ_T)     /* 4096 */
#define EPS_LN  1e-5f

// ---------------------------------------------------------------------------
// Static device scratch
// ---------------------------------------------------------------------------
__device__ float g_h   [MROWS * D_MODEL];
__device__ float g_ln  [MROWS * D_MODEL];
__device__ float g_qkv [MROWS * 3 * D_MODEL];
__device__ float g_attn[MROWS * D_MODEL];
__device__ float g_ff  [MROWS * D_FF];

// ---------------------------------------------------------------------------
// Embedding
// ---------------------------------------------------------------------------
__global__ void embed_kernel(const int* __restrict__ x,
                             const float* __restrict__ tok,
                             const float* __restrict__ pos,
                             float* __restrict__ h) {
    int i = blockIdx.x * blockDim.x + threadIdx.x;
    if (i >= MROWS * D_MODEL) return;
    int d   = i & (D_MODEL - 1);
    int row = i >> 9;
    int t   = row & (SEQ_T - 1);
    int tok_id = x[row];
    h[i] = tok[tok_id * D_MODEL + d] + pos[t * D_MODEL + d];
}

// ---------------------------------------------------------------------------
// LayerNorm
// ---------------------------------------------------------------------------
__global__ void ln_kernel(const float* __restrict__ in,
                          const float* __restrict__ w,
                          const float* __restrict__ b,
                          float* __restrict__ out) {
    int row = blockIdx.x;
    int tid = threadIdx.x;
    const float* xr = in + (size_t)row * D_MODEL;

    float v0 = xr[tid];
    float v1 = xr[tid + 256];

    __shared__ float red[256];
    red[tid] = v0 + v1;
    __syncthreads();
    #pragma unroll
    for (int s = 128; s > 0; s >>= 1) {
        if (tid < s) red[tid] += red[tid + s];
        __syncthreads();
    }
    float mu = red[0] * (1.0f / D_MODEL);
    __syncthreads();

    float d0 = v0 - mu, d1 = v1 - mu;
    red[tid] = d0 * d0 + d1 * d1;
    __syncthreads();
    #pragma unroll
    for (int s = 128; s > 0; s >>= 1) {
        if (tid < s) red[tid] += red[tid + s];
        __syncthreads();
    }
    float rstd = rsqrtf(red[0] * (1.0f / D_MODEL) + EPS_LN);

    float* orow = out + (size_t)row * D_MODEL;
    orow[tid]       = d0 * rstd * w[tid]       + b[tid];
    orow[tid + 256] = d1 * rstd * w[tid + 256] + b[tid + 256];
}

// ---------------------------------------------------------------------------
// tf32 tensor-core GEMM (unchanged from R5)
// ---------------------------------------------------------------------------
__device__ __forceinline__ float gelu_exact(float x) {
    return 0.5f * x * (1.0f + erff(x * 0.70710678118654752f));
}

__device__ __forceinline__ unsigned f2tf(float f) {
    unsigned u;
    asm("cvt.rna.tf32.f32 %0, %1;" : "=r"(u) : "f"(f));
    return u;
}

template <int EPI>
__global__ __launch_bounds__(256, 2)
void gemm_tf32_kernel(const float* __restrict__ X,
                      const float* __restrict__ W,
                      float* __restrict__ Y,
                      int M, int N, int K) {
    __shared__ unsigned Xs[32][132];
    __shared__ unsigned Ws[32][132];

    int tid = threadIdx.x;
    int w = tid >> 5, l = tid & 31;
    int wm = w & 3;
    int wn = w >> 2;
    int g = l >> 2, t = l & 3;
    int rowBase = blockIdx.y * 128;
    int colBase = blockIdx.x * 128;

    int lm = tid & 127;
    int ks = (tid >> 7) * 16;
    const float* xp = X + (size_t)(rowBase + lm) * K + ks;
    const float* wp = W + (size_t)(colBase + lm) * K + ks;

    float acc[2][8][4];
    #pragma unroll
    for (int i = 0; i < 2; i++)
        #pragma unroll
        for (int j = 0; j < 8; j++)
            #pragma unroll
            for (int c = 0; c < 4; c++) acc[i][j][c] = 0.0f;

    int nBK = K >> 5;
    for (int kt = 0; kt < nBK; kt++) {
        int koff = kt << 5;
        #pragma unroll
        for (int c = 0; c < 4; c++) {
            float4 xv = *(const float4*)(xp + koff + c * 4);
            float4 wv = *(const float4*)(wp + koff + c * 4);
            Xs[ks + c * 4 + 0][lm] = f2tf(xv.x);
            Xs[ks + c * 4 + 1][lm] = f2tf(xv.y);
            Xs[ks + c * 4 + 2][lm] = f2tf(xv.z);
            Xs[ks + c * 4 + 3][lm] = f2tf(xv.w);
            Ws[ks + c * 4 + 0][lm] = f2tf(wv.x);
            Ws[ks + c * 4 + 1][lm] = f2tf(wv.y);
            Ws[ks + c * 4 + 2][lm] = f2tf(wv.z);
            Ws[ks + c * 4 + 3][lm] = f2tf(wv.w);
        }
        __syncthreads();

        #pragma unroll
        for (int kb = 0; kb < 32; kb += 8) {
            unsigned a[2][4];
            #pragma unroll
            for (int i = 0; i < 2; i++) {
                int mB = wm * 32 + i * 16;
                a[i][0] = Xs[kb + t]    [mB + g];
                a[i][1] = Xs[kb + t]    [mB + g + 8];
                a[i][2] = Xs[kb + t + 4][mB + g];
                a[i][3] = Xs[kb + t + 4][mB + g + 8];
            }
            #pragma unroll
            for (int j = 0; j < 8; j++) {
                int nB = wn * 64 + j * 8;
                unsigned b0 = Ws[kb + t]    [nB + g];
                unsigned b1 = Ws[kb + t + 4][nB + g];
                #pragma unroll
                for (int i = 0; i < 2; i++) {
                    asm volatile(
                        "mma.sync.aligned.m16n8k8.row.col.f32.tf32.tf32.f32 "
                        "{%0,%1,%2,%3}, {%4,%5,%6,%7}, {%8,%9}, {%0,%1,%2,%3};"
                        : "+f"(acc[i][j][0]), "+f"(acc[i][j][1]),
                          "+f"(acc[i][j][2]), "+f"(acc[i][j][3])
                        : "r"(a[i][0]), "r"(a[i][1]), "r"(a[i][2]), "r"(a[i][3]),
                          "r"(b0), "r"(b1));
                }
            }
        }
        __syncthreads();
    }

    #pragma unroll
    for (int i = 0; i < 2; i++) {
        int r0 = rowBase + wm * 32 + i * 16 + g;
        #pragma unroll
        for (int j = 0; j < 8; j++) {
            int n = colBase + wn * 64 + j * 8 + 2 * t;
            size_t i0 = (size_t)r0 * N + n;
            size_t i1 = (size_t)(r0 + 8) * N + n;
            if (EPI == 0) {
                *(float2*)&Y[i0] = make_float2(acc[i][j][0], acc[i][j][1]);
                *(float2*)&Y[i1] = make_float2(acc[i][j][2], acc[i][j][3]);
            } else if (EPI == 1) {
                float2 y0 = *(float2*)&Y[i0];
                float2 y1 = *(float2*)&Y[i1];
                y0.x += acc[i][j][0]; y0.y += acc[i][j][1];
                y1.x += acc[i][j][2]; y1.y += acc[i][j][3];
                *(float2*)&Y[i0] = y0;
                *(float2*)&Y[i1] = y1;
            } else {
                *(float2*)&Y[i0] = make_float2(gelu_exact(acc[i][j][0]),
                                               gelu_exact(acc[i][j][1]));
                *(float2*)&Y[i1] = make_float2(gelu_exact(acc[i][j][2]),
                                               gelu_exact(acc[i][j][3]));
            }
        }
    }
}

// ---------------------------------------------------------------------------
// Flash attention v2: BQ=128, BK=64, 256 threads, 4q x 8k microtile, fp32.
// Dynamic smem: Qs^T [64][128] | Ks^T [64][64] | Ps [128][68] | Vs [64][64]
// ---------------------------------------------------------------------------
#define QS_OFF 0
#define KS_OFF 8192
#define PS_OFF 12288
#define VS_OFF 20992
#define FATTN_SMEM (25088 * 4)

__global__ __launch_bounds__(256, 2)
void fattn2_kernel(const float* __restrict__ qkv,
                   float* __restrict__ out) {
    extern __shared__ float sm[];
    float* Qs = sm + QS_OFF;   // [d][q] 64 x 128
    float* Ks = sm + KS_OFF;   // [d][k] 64 x 64
    float* Ps = sm + PS_OFF;   // [q][k] 128 x 68 (stride 68)
    float* Vs = sm + VS_OFF;   // [k][d] 64 x 64

    int qt = blockIdx.x;       // 0..15
    int h  = blockIdx.y;
    int b  = blockIdx.z;
    int tid = threadIdx.x;
    int tx = tid & 7;          // 8 k-cols
    int ty = tid >> 3;         // 32 -> 4 q-rows each

    size_t base = (size_t)b * SEQ_T * (3 * D_MODEL);

    // Load Q tile transposed: 128 rows x 64 d
    {
        int lq = tid & 127;
        int dh = (tid >> 7) * 32;
        const float* qb = qkv + base + (size_t)(qt * 128 + lq) * (3 * D_MODEL)
                        + h * D_HEAD + dh;
        #pragma unroll
        for (int it = 0; it < 8; it++) {
            float4 v = *(const float4*)(qb + it * 4);
            Qs[(dh + it * 4 + 0) * 128 + lq] = v.x;
            Qs[(dh + it * 4 + 1) * 128 + lq] = v.y;
            Qs[(dh + it * 4 + 2) * 128 + lq] = v.z;
            Qs[(dh + it * 4 + 3) * 128 + lq] = v.w;
        }
    }

    float accO[4][8];
    #pragma unroll
    for (int i = 0; i < 4; i++)
        #pragma unroll
        for (int j = 0; j < 8; j++) accO[i][j] = 0.0f;
    float m_i[4] = {-1e30f, -1e30f, -1e30f, -1e30f};
    float l_i[4] = {0.0f, 0.0f, 0.0f, 0.0f};

    int nKT = 2 * qt + 2;      // k-tiles 0 .. 2qt+1

    for (int kt = 0; kt < nKT; kt++) {
        __syncthreads();   // protect K/V/P buffers from previous iteration readers

        // Load K tile transposed [d][k]
        {
            int lk = tid & 63;
            int dh = (tid >> 6) * 16;
            const float* kb = qkv + base + (size_t)(kt * 64 + lk) * (3 * D_MODEL)
                            + D_MODEL + h * D_HEAD + dh;
            #pragma unroll
            for (int it = 0; it < 4; it++) {
                float4 v = *(const float4*)(kb + it * 4);
                Ks[(dh + it * 4 + 0) * 64 + lk] = v.x;
                Ks[(dh + it * 4 + 1) * 64 + lk] = v.y;
                Ks[(dh + it * 4 + 2) * 64 + lk] = v.z;
                Ks[(dh + it * 4 + 3) * 64 + lk] = v.w;
            }
        }
        // Load V tile [k][d]
        #pragma unroll
        for (int it = 0; it < 4; it++) {
            int fi = it * 256 + tid;
            int kr = fi >> 4;
            int c4 = (fi & 15) * 4;
            const float* vb = qkv + base + (size_t)(kt * 64 + kr) * (3 * D_MODEL)
                            + 2 * D_MODEL + h * D_HEAD + c4;
            *(float4*)&Vs[kr * 64 + c4] = *(const float4*)vb;
        }
        __syncthreads();

        // S = Q K^T  (4q x 8k per thread)
        float s[4][8];
        #pragma unroll
        for (int i = 0; i < 4; i++)
            #pragma unroll
            for (int j = 0; j < 8; j++) s[i][j] = 0.0f;

        #pragma unroll 8
        for (int d = 0; d < 64; d++) {
            float4 qa = *(const float4*)&Qs[d * 128 + ty * 4];
            float4 ka = *(const float4*)&Ks[d * 64 + tx * 8];
            float4 kb = *(const float4*)&Ks[d * 64 + tx * 8 + 4];
            float a[4]  = {qa.x, qa.y, qa.z, qa.w};
            float kv[8] = {ka.x, ka.y, ka.z, ka.w, kb.x, kb.y, kb.z, kb.w};
            #pragma unroll
            for (int i = 0; i < 4; i++)
                #pragma unroll
                for (int j = 0; j < 8; j++)
                    s[i][j] += a[i] * kv[j];
        }

        // scale + causal mask (only needed on the top two diagonal tiles)
        bool need_mask = (kt >= 2 * qt);
        #pragma unroll
        for (int i = 0; i < 4; i++)
            #pragma unroll
            for (int j = 0; j < 8; j++) {
                s[i][j] *= 0.125f;
                if (need_mask) {
                    int kloc = kt * 64 + tx * 8 + j;
                    int qloc = qt * 128 + ty * 4 + i;
                    if (kloc > qloc) s[i][j] = -1e30f;
                }
            }

        // online softmax (reduction across 8 tx lanes via shfl)
        float p[4][8];
        #pragma unroll
        for (int i = 0; i < 4; i++) {
            float rmax = s[i][0];
            #pragma unroll
            for (int j = 1; j < 8; j++) rmax = fmaxf(rmax, s[i][j]);
            #pragma unroll
            for (int off = 1; off < 8; off <<= 1)
                rmax = fmaxf(rmax, __shfl_xor_sync(0xffffffffu, rmax, off));
            float m_new = fmaxf(m_i[i], rmax);
            float scale = __expf(m_i[i] - m_new);
            float rs = 0.0f;
            #pragma unroll
            for (int j = 0; j < 8; j++) {
                p[i][j] = __expf(s[i][j] - m_new);
                rs += p[i][j];
            }
            #pragma unroll
            for (int off = 1; off < 8; off <<= 1)
                rs += __shfl_xor_sync(0xffffffffu, rs, off);
            l_i[i] = l_i[i] * scale + rs;
            m_i[i] = m_new;
            #pragma unroll
            for (int j = 0; j < 8; j++) accO[i][j] *= scale;
        }

        // store P [q][k] stride 68
        #pragma unroll
        for (int i = 0; i < 4; i++) {
            *(float4*)&Ps[(ty * 4 + i) * 68 + tx * 8] =
                make_float4(p[i][0], p[i][1], p[i][2], p[i][3]);
            *(float4*)&Ps[(ty * 4 + i) * 68 + tx * 8 + 4] =
                make_float4(p[i][4], p[i][5], p[i][6], p[i][7]);
        }
        __syncthreads();

        // O += P V  (thread owns 4 q-rows x 8 d-cols at tx*8)
        #pragma unroll 4
        for (int kc = 0; kc < 16; kc++) {
            float4 pv[4];
            #pragma unroll
            for (int i = 0; i < 4; i++)
                pv[i] = *(const float4*)&Ps[(ty * 4 + i) * 68 + kc * 4];
            #pragma unroll
            for (int kk = 0; kk < 4; kk++) {
                int k = kc * 4 + kk;
                float4 va = *(const float4*)&Vs[k * 64 + tx * 8];
                float4 vb = *(const float4*)&Vs[k * 64 + tx * 8 + 4];
                float v8[8] = {va.x, va.y, va.z, va.w, vb.x, vb.y, vb.z, vb.w};
                #pragma unroll
                for (int i = 0; i < 4; i++) {
                    float pk = (kk == 0) ? pv[i].x : (kk == 1) ? pv[i].y
                             : (kk == 2) ? pv[i].z : pv[i].w;
                    #pragma unroll
                    for (int j = 0; j < 8; j++)
                        accO[i][j] += pk * v8[j];
                }
            }
        }
    }

    // epilogue
    #pragma unroll
    for (int i = 0; i < 4; i++) {
        float inv = 1.0f / l_i[i];
        size_t row = (size_t)(b * SEQ_T + qt * 128 + ty * 4 + i);
        float* orow = out + row * D_MODEL + h * D_HEAD + tx * 8;
        *(float4*)&orow[0] = make_float4(accO[i][0] * inv, accO[i][1] * inv,
                                         accO[i][2] * inv, accO[i][3] * inv);
        *(float4*)&orow[4] = make_float4(accO[i][4] * inv, accO[i][5] * inv,
                                         accO[i][6] * inv, accO[i][7] * inv);
    }
}

// ---------------------------------------------------------------------------
// Host launcher
// ---------------------------------------------------------------------------
extern "C" void kernel_launch(void* const* d_in, const int* in_sizes, int n_in,
                              void* d_out, int out_size) {
    const int*   x       = (const int*)  d_in[0];
    const float* tok_emb = (const float*)d_in[1];
    const float* pos_emb = (const float*)d_in[2];
    const float* qkv_w   = (const float*)d_in[3];
    const float* proj_w  = (const float*)d_in[4];
    const float* ln1_w   = (const float*)d_in[5];
    const float* ln1_b   = (const float*)d_in[6];
    const float* ln2_w   = (const float*)d_in[7];
    const float* ln2_b   = (const float*)d_in[8];
    const float* fc1_w   = (const float*)d_in[9];
    const float* fc2_w   = (const float*)d_in[10];
    const float* lnf_w   = (const float*)d_in[11];
    const float* lnf_b   = (const float*)d_in[12];
    const float* head_w  = (const float*)d_in[13];
    float* out = (float*)d_out;

    float *ph, *pln, *pqkv, *pattn, *pff;
    cudaGetSymbolAddress((void**)&ph,    g_h);
    cudaGetSymbolAddress((void**)&pln,   g_ln);
    cudaGetSymbolAddress((void**)&pqkv,  g_qkv);
    cudaGetSymbolAddress((void**)&pattn, g_attn);
    cudaGetSymbolAddress((void**)&pff,   g_ff);

    cudaFuncSetAttribute(fattn2_kernel,
                         cudaFuncAttributeMaxDynamicSharedMemorySize, FATTN_SMEM);

    embed_kernel<<<(MROWS * D_MODEL + 255) / 256, 256>>>(x, tok_emb, pos_emb, ph);

    for (int l = 0; l < DEPTH; l++) {
        const float* qw  = qkv_w  + (size_t)l * 3 * D_MODEL * D_MODEL;
        const float* pw  = proj_w + (size_t)l * D_MODEL * D_MODEL;
        const float* f1w = fc1_w  + (size_t)l * D_FF * D_MODEL;
        const float* f2w = fc2_w  + (size_t)l * D_MODEL * D_FF;

        ln_kernel<<<MROWS, 256>>>(ph, ln1_w + l * D_MODEL, ln1_b + l * D_MODEL, pln);

        gemm_tf32_kernel<0><<<dim3(3 * D_MODEL / 128, MROWS / 128), 256>>>(
            pln, qw, pqkv, MROWS, 3 * D_MODEL, D_MODEL);

        fattn2_kernel<<<dim3(SEQ_T / 128, N_HEADS, BB), 256, FATTN_SMEM>>>(pqkv, pattn);

        gemm_tf32_kernel<1><<<dim3(D_MODEL / 128, MROWS / 128), 256>>>(
            pattn, pw, ph, MROWS, D_MODEL, D_MODEL);

        ln_kernel<<<MROWS, 256>>>(ph, ln2_w + l * D_MODEL, ln2_b + l * D_MODEL, pln);

        gemm_tf32_kernel<2><<<dim3(D_FF / 128, MROWS / 128), 256>>>(
            pln, f1w, pff, MROWS, D_FF, D_MODEL);

        gemm_tf32_kernel<1><<<dim3(D_MODEL / 128, MROWS / 128), 256>>>(
            pff, f2w, ph, MROWS, D_MODEL, D_FF);
    }

    ln_kernel<<<MROWS, 256>>>(ph, lnf_w, lnf_b, pln);
    gemm_tf32_kernel<0><<<dim3(VOCAB / 128, MROWS / 128), 256>>>(
        pln, head_w, out, MROWS, VOCAB, D_MODEL);

    (void)in_sizes; (void)n_in; (void)out_size;
}

// round 8
// speedup vs baseline: 1.4844x; 1.4844x over previous
#include <cuda_runtime.h>
#include <math.h>

#define DEPTH   6
#define D_MODEL 512
#define N_HEADS 8
#define D_HEAD  64
#define D_FF    2048
#define SEQ_T   2048
#define VOCAB   256
#define BB      2
#define MROWS   (BB * SEQ_T)     /* 4096 */
#define EPS_LN  1e-5f

// ---------------------------------------------------------------------------
// Static device scratch
// ---------------------------------------------------------------------------
__device__ float g_h   [MROWS * D_MODEL];
__device__ float g_ln  [MROWS * D_MODEL];
__device__ float g_qkv [MROWS * 3 * D_MODEL];
__device__ float g_attn[MROWS * D_MODEL];
__device__ float g_ff  [MROWS * D_FF];

// ---------------------------------------------------------------------------
// Embedding
// ---------------------------------------------------------------------------
__global__ void embed_kernel(const int* __restrict__ x,
                             const float* __restrict__ tok,
                             const float* __restrict__ pos,
                             float* __restrict__ h) {
    int i = blockIdx.x * blockDim.x + threadIdx.x;
    if (i >= MROWS * D_MODEL) return;
    int d   = i & (D_MODEL - 1);
    int row = i >> 9;
    int t   = row & (SEQ_T - 1);
    int tok_id = x[row];
    h[i] = tok[tok_id * D_MODEL + d] + pos[t * D_MODEL + d];
}

// ---------------------------------------------------------------------------
// LayerNorm
// ---------------------------------------------------------------------------
__global__ void ln_kernel(const float* __restrict__ in,
                          const float* __restrict__ w,
                          const float* __restrict__ b,
                          float* __restrict__ out) {
    int row = blockIdx.x;
    int tid = threadIdx.x;
    const float* xr = in + (size_t)row * D_MODEL;

    float v0 = xr[tid];
    float v1 = xr[tid + 256];

    __shared__ float red[256];
    red[tid] = v0 + v1;
    __syncthreads();
    #pragma unroll
    for (int s = 128; s > 0; s >>= 1) {
        if (tid < s) red[tid] += red[tid + s];
        __syncthreads();
    }
    float mu = red[0] * (1.0f / D_MODEL);
    __syncthreads();

    float d0 = v0 - mu, d1 = v1 - mu;
    red[tid] = d0 * d0 + d1 * d1;
    __syncthreads();
    #pragma unroll
    for (int s = 128; s > 0; s >>= 1) {
        if (tid < s) red[tid] += red[tid + s];
        __syncthreads();
    }
    float rstd = rsqrtf(red[0] * (1.0f / D_MODEL) + EPS_LN);

    float* orow = out + (size_t)row * D_MODEL;
    orow[tid]       = d0 * rstd * w[tid]       + b[tid];
    orow[tid + 256] = d1 * rstd * w[tid + 256] + b[tid + 256];
}

// ---------------------------------------------------------------------------
// tf32 tensor-core GEMM v2: double-buffered smem (stride 136, conflict-free),
// register prefetch. Y[M,N] = X[M,K] @ W[N,K]^T. 128x128 tile, BK=32.
// ---------------------------------------------------------------------------
__device__ __forceinline__ float gelu_exact(float x) {
    return 0.5f * x * (1.0f + erff(x * 0.70710678118654752f));
}

__device__ __forceinline__ unsigned f2tf(float f) {
    unsigned u;
    asm("cvt.rna.tf32.f32 %0, %1;" : "=r"(u) : "f"(f));
    return u;
}

#define GSTRIDE 136
#define GBUF    (32 * GSTRIDE)
#define GEMM_SMEM (4 * GBUF * 4)   /* 2 bufs x (X+W) = 4*GBUF unsigned */

template <int EPI>
__global__ __launch_bounds__(256, 2)
void gemm_tf32_kernel(const float* __restrict__ X,
                      const float* __restrict__ W,
                      float* __restrict__ Y,
                      int M, int N, int K) {
    extern __shared__ unsigned smu[];
    unsigned* Xs = smu;             // [2][32][GSTRIDE]
    unsigned* Ws = smu + 2 * GBUF;  // [2][32][GSTRIDE]

    int tid = threadIdx.x;
    int w = tid >> 5, l = tid & 31;
    int wm = w & 3;
    int wn = w >> 2;
    int g = l >> 2, t = l & 3;
    int rowBase = blockIdx.y * 128;
    int colBase = blockIdx.x * 128;

    int lm = tid & 127;
    int ks = (tid >> 7) * 16;
    const float* xp = X + (size_t)(rowBase + lm) * K + ks;
    const float* wp = W + (size_t)(colBase + lm) * K + ks;

    float acc[2][8][4];
    #pragma unroll
    for (int i = 0; i < 2; i++)
        #pragma unroll
        for (int j = 0; j < 8; j++)
            #pragma unroll
            for (int c = 0; c < 4; c++) acc[i][j][c] = 0.0f;

    float4 rx[4], rw[4];
    #pragma unroll
    for (int c = 0; c < 4; c++) {
        rx[c] = *(const float4*)(xp + c * 4);
        rw[c] = *(const float4*)(wp + c * 4);
    }
    // store tile 0
    #pragma unroll
    for (int c = 0; c < 4; c++) {
        int kr = ks + c * 4;
        Xs[(kr + 0) * GSTRIDE + lm] = f2tf(rx[c].x);
        Xs[(kr + 1) * GSTRIDE + lm] = f2tf(rx[c].y);
        Xs[(kr + 2) * GSTRIDE + lm] = f2tf(rx[c].z);
        Xs[(kr + 3) * GSTRIDE + lm] = f2tf(rx[c].w);
        Ws[(kr + 0) * GSTRIDE + lm] = f2tf(rw[c].x);
        Ws[(kr + 1) * GSTRIDE + lm] = f2tf(rw[c].y);
        Ws[(kr + 2) * GSTRIDE + lm] = f2tf(rw[c].z);
        Ws[(kr + 3) * GSTRIDE + lm] = f2tf(rw[c].w);
    }
    __syncthreads();

    int nBK = K >> 5;
    for (int kt = 0; kt < nBK; kt++) {
        int cur = kt & 1;
        bool more = (kt + 1 < nBK);
        if (more) {
            int koff = (kt + 1) << 5;
            #pragma unroll
            for (int c = 0; c < 4; c++) {
                rx[c] = *(const float4*)(xp + koff + c * 4);
                rw[c] = *(const float4*)(wp + koff + c * 4);
            }
        }

        const unsigned* Xc = Xs + cur * GBUF;
        const unsigned* Wc = Ws + cur * GBUF;
        #pragma unroll
        for (int kb = 0; kb < 32; kb += 8) {
            unsigned a[2][4];
            #pragma unroll
            for (int i = 0; i < 2; i++) {
                int mB = wm * 32 + i * 16;
                a[i][0] = Xc[(kb + t)     * GSTRIDE + mB + g];
                a[i][1] = Xc[(kb + t)     * GSTRIDE + mB + g + 8];
                a[i][2] = Xc[(kb + t + 4) * GSTRIDE + mB + g];
                a[i][3] = Xc[(kb + t + 4) * GSTRIDE + mB + g + 8];
            }
            #pragma unroll
            for (int j = 0; j < 8; j++) {
                int nB = wn * 64 + j * 8;
                unsigned b0 = Wc[(kb + t)     * GSTRIDE + nB + g];
                unsigned b1 = Wc[(kb + t + 4) * GSTRIDE + nB + g];
                #pragma unroll
                for (int i = 0; i < 2; i++) {
                    asm volatile(
                        "mma.sync.aligned.m16n8k8.row.col.f32.tf32.tf32.f32 "
                        "{%0,%1,%2,%3}, {%4,%5,%6,%7}, {%8,%9}, {%0,%1,%2,%3};"
                        : "+f"(acc[i][j][0]), "+f"(acc[i][j][1]),
                          "+f"(acc[i][j][2]), "+f"(acc[i][j][3])
                        : "r"(a[i][0]), "r"(a[i][1]), "r"(a[i][2]), "r"(a[i][3]),
                          "r"(b0), "r"(b1));
                }
            }
        }

        if (more) {
            unsigned* Xa = Xs + (cur ^ 1) * GBUF;
            unsigned* Wa = Ws + (cur ^ 1) * GBUF;
            #pragma unroll
            for (int c = 0; c < 4; c++) {
                int kr = ks + c * 4;
                Xa[(kr + 0) * GSTRIDE + lm] = f2tf(rx[c].x);
                Xa[(kr + 1) * GSTRIDE + lm] = f2tf(rx[c].y);
                Xa[(kr + 2) * GSTRIDE + lm] = f2tf(rx[c].z);
                Xa[(kr + 3) * GSTRIDE + lm] = f2tf(rx[c].w);
                Wa[(kr + 0) * GSTRIDE + lm] = f2tf(rw[c].x);
                Wa[(kr + 1) * GSTRIDE + lm] = f2tf(rw[c].y);
                Wa[(kr + 2) * GSTRIDE + lm] = f2tf(rw[c].z);
                Wa[(kr + 3) * GSTRIDE + lm] = f2tf(rw[c].w);
            }
            __syncthreads();
        }
    }

    #pragma unroll
    for (int i = 0; i < 2; i++) {
        int r0 = rowBase + wm * 32 + i * 16 + g;
        #pragma unroll
        for (int j = 0; j < 8; j++) {
            int n = colBase + wn * 64 + j * 8 + 2 * t;
            size_t i0 = (size_t)r0 * N + n;
            size_t i1 = (size_t)(r0 + 8) * N + n;
            if (EPI == 0) {
                *(float2*)&Y[i0] = make_float2(acc[i][j][0], acc[i][j][1]);
                *(float2*)&Y[i1] = make_float2(acc[i][j][2], acc[i][j][3]);
            } else if (EPI == 1) {
                float2 y0 = *(float2*)&Y[i0];
                float2 y1 = *(float2*)&Y[i1];
                y0.x += acc[i][j][0]; y0.y += acc[i][j][1];
                y1.x += acc[i][j][2]; y1.y += acc[i][j][3];
                *(float2*)&Y[i0] = y0;
                *(float2*)&Y[i1] = y1;
            } else {
                *(float2*)&Y[i0] = make_float2(gelu_exact(acc[i][j][0]),
                                               gelu_exact(acc[i][j][1]));
                *(float2*)&Y[i1] = make_float2(gelu_exact(acc[i][j][2]),
                                               gelu_exact(acc[i][j][3]));
            }
        }
    }
}

// ---------------------------------------------------------------------------
// Flash attention (R5 proven version: BQ=64, 346us/launch)
// ---------------------------------------------------------------------------
__global__ __launch_bounds__(256)
void fattn_kernel(const float* __restrict__ qkv,
                  float* __restrict__ out) {
    int qt = blockIdx.x;
    int h  = blockIdx.y;
    int b  = blockIdx.z;
    int tid = threadIdx.x;
    int tx = tid & 15;
    int ty = tid >> 4;

    __shared__ float Qs[64][64];
    __shared__ float KPs[64][64];
    __shared__ float Vs[64][64];

    int lq = tid & 63;
    int dg = (tid >> 6) * 16;

    {
        const float* qb = qkv + ((size_t)(b * SEQ_T + qt * 64 + lq)) * (3 * D_MODEL)
                        + h * D_HEAD;
        #pragma unroll
        for (int it = 0; it < 4; it++) {
            float4 v = *(const float4*)(qb + dg + it * 4);
            Qs[dg + it * 4 + 0][lq] = v.x;
            Qs[dg + it * 4 + 1][lq] = v.y;
            Qs[dg + it * 4 + 2][lq] = v.z;
            Qs[dg + it * 4 + 3][lq] = v.w;
        }
    }

    float accO[4][4];
    #pragma unroll
    for (int i = 0; i < 4; i++)
        #pragma unroll
        for (int j = 0; j < 4; j++) accO[i][j] = 0.0f;
    float m_i[4] = {-1e30f, -1e30f, -1e30f, -1e30f};
    float l_i[4] = {0.0f, 0.0f, 0.0f, 0.0f};

    __syncthreads();

    for (int kt = 0; kt <= qt; kt++) {
        {
            const float* kb = qkv + ((size_t)(b * SEQ_T + kt * 64 + lq)) * (3 * D_MODEL)
                            + D_MODEL + h * D_HEAD;
            #pragma unroll
            for (int it = 0; it < 4; it++) {
                float4 v = *(const float4*)(kb + dg + it * 4);
                KPs[dg + it * 4 + 0][lq] = v.x;
                KPs[dg + it * 4 + 1][lq] = v.y;
                KPs[dg + it * 4 + 2][lq] = v.z;
                KPs[dg + it * 4 + 3][lq] = v.w;
            }
            #pragma unroll
            for (int it = 0; it < 4; it++) {
                int f = it * 256 + tid;
                int kk = f >> 4;
                int d4 = (f & 15) * 4;
                const float* vb = qkv + ((size_t)(b * SEQ_T + kt * 64 + kk)) * (3 * D_MODEL)
                                + 2 * D_MODEL + h * D_HEAD + d4;
                float4 v = *(const float4*)vb;
                *(float4*)&Vs[kk][d4] = v;
            }
        }
        __syncthreads();

        float s[4][4];
        #pragma unroll
        for (int i = 0; i < 4; i++)
            #pragma unroll
            for (int j = 0; j < 4; j++) s[i][j] = 0.0f;

        #pragma unroll 8
        for (int d = 0; d < 64; d++) {
            float4 qa = *(const float4*)&Qs[d][ty * 4];
            float4 ka = *(const float4*)&KPs[d][tx * 4];
            float a[4] = {qa.x, qa.y, qa.z, qa.w};
            float kv[4] = {ka.x, ka.y, ka.z, ka.w};
            #pragma unroll
            for (int i = 0; i < 4; i++)
                #pragma unroll
                for (int j = 0; j < 4; j++)
                    s[i][j] += a[i] * kv[j];
        }

        #pragma unroll
        for (int i = 0; i < 4; i++)
            #pragma unroll
            for (int j = 0; j < 4; j++) {
                s[i][j] *= 0.125f;
                if (kt == qt) {
                    int gq = ty * 4 + i;
                    int gk = tx * 4 + j;
                    if (gk > gq) s[i][j] = -1e30f;
                }
            }

        float p[4][4];
        #pragma unroll
        for (int i = 0; i < 4; i++) {
            float rmax = fmaxf(fmaxf(s[i][0], s[i][1]), fmaxf(s[i][2], s[i][3]));
            #pragma unroll
            for (int off = 1; off < 16; off <<= 1)
                rmax = fmaxf(rmax, __shfl_xor_sync(0xffffffffu, rmax, off));
            float m_new = fmaxf(m_i[i], rmax);
            float scale = __expf(m_i[i] - m_new);
            float rs = 0.0f;
            #pragma unroll
            for (int j = 0; j < 4; j++) {
                p[i][j] = __expf(s[i][j] - m_new);
                rs += p[i][j];
            }
            #pragma unroll
            for (int off = 1; off < 16; off <<= 1)
                rs += __shfl_xor_sync(0xffffffffu, rs, off);
            l_i[i] = l_i[i] * scale + rs;
            m_i[i] = m_new;
            #pragma unroll
            for (int j = 0; j < 4; j++) accO[i][j] *= scale;
        }

        __syncthreads();

        #pragma unroll
        for (int i = 0; i < 4; i++)
            *(float4*)&KPs[ty * 4 + i][tx * 4] =
                make_float4(p[i][0], p[i][1], p[i][2], p[i][3]);
        __syncthreads();

        #pragma unroll 4
        for (int k = 0; k < 64; k++) {
            float4 vv = *(const float4*)&Vs[k][tx * 4];
            float v4[4] = {vv.x, vv.y, vv.z, vv.w};
            #pragma unroll
            for (int i = 0; i < 4; i++) {
                float pk = KPs[ty * 4 + i][k];
                #pragma unroll
                for (int j = 0; j < 4; j++)
                    accO[i][j] += pk * v4[j];
            }
        }
        __syncthreads();
    }

    #pragma unroll
    for (int i = 0; i < 4; i++) {
        float inv = 1.0f / l_i[i];
        size_t row = (size_t)(b * SEQ_T + qt * 64 + ty * 4 + i);
        float* orow = out + row * D_MODEL + h * D_HEAD + tx * 4;
        orow[0] = accO[i][0] * inv;
        orow[1] = accO[i][1] * inv;
        orow[2] = accO[i][2] * inv;
        orow[3] = accO[i][3] * inv;
    }
}

// ---------------------------------------------------------------------------
// Host launcher
// ---------------------------------------------------------------------------
extern "C" void kernel_launch(void* const* d_in, const int* in_sizes, int n_in,
                              void* d_out, int out_size) {
    const int*   x       = (const int*)  d_in[0];
    const float* tok_emb = (const float*)d_in[1];
    const float* pos_emb = (const float*)d_in[2];
    const float* qkv_w   = (const float*)d_in[3];
    const float* proj_w  = (const float*)d_in[4];
    const float* ln1_w   = (const float*)d_in[5];
    const float* ln1_b   = (const float*)d_in[6];
    const float* ln2_w   = (const float*)d_in[7];
    const float* ln2_b   = (const float*)d_in[8];
    const float* fc1_w   = (const float*)d_in[9];
    const float* fc2_w   = (const float*)d_in[10];
    const float* lnf_w   = (const float*)d_in[11];
    const float* lnf_b   = (const float*)d_in[12];
    const float* head_w  = (const float*)d_in[13];
    float* out = (float*)d_out;

    float *ph, *pln, *pqkv, *pattn, *pff;
    cudaGetSymbolAddress((void**)&ph,    g_h);
    cudaGetSymbolAddress((void**)&pln,   g_ln);
    cudaGetSymbolAddress((void**)&pqkv,  g_qkv);
    cudaGetSymbolAddress((void**)&pattn, g_attn);
    cudaGetSymbolAddress((void**)&pff,   g_ff);

    cudaFuncSetAttribute(gemm_tf32_kernel<0>,
                         cudaFuncAttributeMaxDynamicSharedMemorySize, GEMM_SMEM);
    cudaFuncSetAttribute(gemm_tf32_kernel<1>,
                         cudaFuncAttributeMaxDynamicSharedMemorySize, GEMM_SMEM);
    cudaFuncSetAttribute(gemm_tf32_kernel<2>,
                         cudaFuncAttributeMaxDynamicSharedMemorySize, GEMM_SMEM);

    embed_kernel<<<(MROWS * D_MODEL + 255) / 256, 256>>>(x, tok_emb, pos_emb, ph);

    for (int l = 0; l < DEPTH; l++) {
        const float* qw  = qkv_w  + (size_t)l * 3 * D_MODEL * D_MODEL;
        const float* pw  = proj_w + (size_t)l * D_MODEL * D_MODEL;
        const float* f1w = fc1_w  + (size_t)l * D_FF * D_MODEL;
        const float* f2w = fc2_w  + (size_t)l * D_MODEL * D_FF;

        ln_kernel<<<MROWS, 256>>>(ph, ln1_w + l * D_MODEL, ln1_b + l * D_MODEL, pln);

        gemm_tf32_kernel<0><<<dim3(3 * D_MODEL / 128, MROWS / 128), 256, GEMM_SMEM>>>(
            pln, qw, pqkv, MROWS, 3 * D_MODEL, D_MODEL);

        fattn_kernel<<<dim3(SEQ_T / 64, N_HEADS, BB), 256>>>(pqkv, pattn);

        gemm_tf32_kernel<1><<<dim3(D_MODEL / 128, MROWS / 128), 256, GEMM_SMEM>>>(
            pattn, pw, ph, MROWS, D_MODEL, D_MODEL);

        ln_kernel<<<MROWS, 256>>>(ph, ln2_w + l * D_MODEL, ln2_b + l * D_MODEL, pln);

        gemm_tf32_kernel<2><<<dim3(D_FF / 128, MROWS / 128), 256, GEMM_SMEM>>>(
            pln, f1w, pff, MROWS, D_FF, D_MODEL);

        gemm_tf32_kernel<1><<<dim3(D_MODEL / 128, MROWS / 128), 256, GEMM_SMEM>>>(
            pff, f2w, ph, MROWS, D_MODEL, D_FF);
    }

    ln_kernel<<<MROWS, 256>>>(ph, lnf_w, lnf_b, pln);
    gemm_tf32_kernel<0><<<dim3(VOCAB / 128, MROWS / 128), 256, GEMM_SMEM>>>(
        pln, head_w, out, MROWS, VOCAB, D_MODEL);

    (void)in_sizes; (void)n_in; (void)out_size;
}

// round 9
// speedup vs baseline: 1.5553x; 1.0478x over previous
#include <cuda_runtime.h>
#include <math.h>

#define DEPTH   6
#define D_MODEL 512
#define N_HEADS 8
#define D_HEAD  64
#define D_FF    2048
#define SEQ_T   2048
#define VOCAB   256
#define BB      2
#define MROWS   (BB * SEQ_T)     /* 4096 */
#define EPS_LN  1e-5f
#define NQT     (SEQ_T / 64)     /* 32 q-tiles */

// ---------------------------------------------------------------------------
// Static device scratch
// ---------------------------------------------------------------------------
__device__ float g_h   [MROWS * D_MODEL];
__device__ float g_ln  [MROWS * D_MODEL];
__device__ float g_qkv [MROWS * 3 * D_MODEL];
__device__ float g_attn[MROWS * D_MODEL];
__device__ float g_ff  [MROWS * D_FF];

// ---------------------------------------------------------------------------
// Embedding
// ---------------------------------------------------------------------------
__global__ void embed_kernel(const int* __restrict__ x,
                             const float* __restrict__ tok,
                             const float* __restrict__ pos,
                             float* __restrict__ h) {
    int i = blockIdx.x * blockDim.x + threadIdx.x;
    if (i >= MROWS * D_MODEL) return;
    int d   = i & (D_MODEL - 1);
    int row = i >> 9;
    int t   = row & (SEQ_T - 1);
    int tok_id = x[row];
    h[i] = tok[tok_id * D_MODEL + d] + pos[t * D_MODEL + d];
}

// ---------------------------------------------------------------------------
// LayerNorm
// ---------------------------------------------------------------------------
__global__ void ln_kernel(const float* __restrict__ in,
                          const float* __restrict__ w,
                          const float* __restrict__ b,
                          float* __restrict__ out) {
    int row = blockIdx.x;
    int tid = threadIdx.x;
    const float* xr = in + (size_t)row * D_MODEL;

    float v0 = xr[tid];
    float v1 = xr[tid + 256];

    __shared__ float red[256];
    red[tid] = v0 + v1;
    __syncthreads();
    #pragma unroll
    for (int s = 128; s > 0; s >>= 1) {
        if (tid < s) red[tid] += red[tid + s];
        __syncthreads();
    }
    float mu = red[0] * (1.0f / D_MODEL);
    __syncthreads();

    float d0 = v0 - mu, d1 = v1 - mu;
    red[tid] = d0 * d0 + d1 * d1;
    __syncthreads();
    #pragma unroll
    for (int s = 128; s > 0; s >>= 1) {
        if (tid < s) red[tid] += red[tid + s];
        __syncthreads();
    }
    float rstd = rsqrtf(red[0] * (1.0f / D_MODEL) + EPS_LN);

    float* orow = out + (size_t)row * D_MODEL;
    orow[tid]       = d0 * rstd * w[tid]       + b[tid];
    orow[tid + 256] = d1 * rstd * w[tid + 256] + b[tid + 256];
}

// ---------------------------------------------------------------------------
// tf32 tensor-core GEMM (R8: double-buffered, stride 136)
// ---------------------------------------------------------------------------
__device__ __forceinline__ float gelu_exact(float x) {
    return 0.5f * x * (1.0f + erff(x * 0.70710678118654752f));
}

__device__ __forceinline__ unsigned f2tf(float f) {
    unsigned u;
    asm("cvt.rna.tf32.f32 %0, %1;" : "=r"(u) : "f"(f));
    return u;
}

#define GSTRIDE 136
#define GBUF    (32 * GSTRIDE)
#define GEMM_SMEM (4 * GBUF * 4)

template <int EPI>
__global__ __launch_bounds__(256, 2)
void gemm_tf32_kernel(const float* __restrict__ X,
                      const float* __restrict__ W,
                      float* __restrict__ Y,
                      int M, int N, int K) {
    extern __shared__ unsigned smu[];
    unsigned* Xs = smu;
    unsigned* Ws = smu + 2 * GBUF;

    int tid = threadIdx.x;
    int w = tid >> 5, l = tid & 31;
    int wm = w & 3;
    int wn = w >> 2;
    int g = l >> 2, t = l & 3;
    int rowBase = blockIdx.y * 128;
    int colBase = blockIdx.x * 128;

    int lm = tid & 127;
    int ks = (tid >> 7) * 16;
    const float* xp = X + (size_t)(rowBase + lm) * K + ks;
    const float* wp = W + (size_t)(colBase + lm) * K + ks;

    float acc[2][8][4];
    #pragma unroll
    for (int i = 0; i < 2; i++)
        #pragma unroll
        for (int j = 0; j < 8; j++)
            #pragma unroll
            for (int c = 0; c < 4; c++) acc[i][j][c] = 0.0f;

    float4 rx[4], rw[4];
    #pragma unroll
    for (int c = 0; c < 4; c++) {
        rx[c] = *(const float4*)(xp + c * 4);
        rw[c] = *(const float4*)(wp + c * 4);
    }
    #pragma unroll
    for (int c = 0; c < 4; c++) {
        int kr = ks + c * 4;
        Xs[(kr + 0) * GSTRIDE + lm] = f2tf(rx[c].x);
        Xs[(kr + 1) * GSTRIDE + lm] = f2tf(rx[c].y);
        Xs[(kr + 2) * GSTRIDE + lm] = f2tf(rx[c].z);
        Xs[(kr + 3) * GSTRIDE + lm] = f2tf(rx[c].w);
        Ws[(kr + 0) * GSTRIDE + lm] = f2tf(rw[c].x);
        Ws[(kr + 1) * GSTRIDE + lm] = f2tf(rw[c].y);
        Ws[(kr + 2) * GSTRIDE + lm] = f2tf(rw[c].z);
        Ws[(kr + 3) * GSTRIDE + lm] = f2tf(rw[c].w);
    }
    __syncthreads();

    int nBK = K >> 5;
    for (int kt = 0; kt < nBK; kt++) {
        int cur = kt & 1;
        bool more = (kt + 1 < nBK);
        if (more) {
            int koff = (kt + 1) << 5;
            #pragma unroll
            for (int c = 0; c < 4; c++) {
                rx[c] = *(const float4*)(xp + koff + c * 4);
                rw[c] = *(const float4*)(wp + koff + c * 4);
            }
        }

        const unsigned* Xc = Xs + cur * GBUF;
        const unsigned* Wc = Ws + cur * GBUF;
        #pragma unroll
        for (int kb = 0; kb < 32; kb += 8) {
            unsigned a[2][4];
            #pragma unroll
            for (int i = 0; i < 2; i++) {
                int mB = wm * 32 + i * 16;
                a[i][0] = Xc[(kb + t)     * GSTRIDE + mB + g];
                a[i][1] = Xc[(kb + t)     * GSTRIDE + mB + g + 8];
                a[i][2] = Xc[(kb + t + 4) * GSTRIDE + mB + g];
                a[i][3] = Xc[(kb + t + 4) * GSTRIDE + mB + g + 8];
            }
            #pragma unroll
            for (int j = 0; j < 8; j++) {
                int nB = wn * 64 + j * 8;
                unsigned b0 = Wc[(kb + t)     * GSTRIDE + nB + g];
                unsigned b1 = Wc[(kb + t + 4) * GSTRIDE + nB + g];
                #pragma unroll
                for (int i = 0; i < 2; i++) {
                    asm volatile(
                        "mma.sync.aligned.m16n8k8.row.col.f32.tf32.tf32.f32 "
                        "{%0,%1,%2,%3}, {%4,%5,%6,%7}, {%8,%9}, {%0,%1,%2,%3};"
                        : "+f"(acc[i][j][0]), "+f"(acc[i][j][1]),
                          "+f"(acc[i][j][2]), "+f"(acc[i][j][3])
                        : "r"(a[i][0]), "r"(a[i][1]), "r"(a[i][2]), "r"(a[i][3]),
                          "r"(b0), "r"(b1));
                }
            }
        }

        if (more) {
            unsigned* Xa = Xs + (cur ^ 1) * GBUF;
            unsigned* Wa = Ws + (cur ^ 1) * GBUF;
            #pragma unroll
            for (int c = 0; c < 4; c++) {
                int kr = ks + c * 4;
                Xa[(kr + 0) * GSTRIDE + lm] = f2tf(rx[c].x);
                Xa[(kr + 1) * GSTRIDE + lm] = f2tf(rx[c].y);
                Xa[(kr + 2) * GSTRIDE + lm] = f2tf(rx[c].z);
                Xa[(kr + 3) * GSTRIDE + lm] = f2tf(rx[c].w);
                Wa[(kr + 0) * GSTRIDE + lm] = f2tf(rw[c].x);
                Wa[(kr + 1) * GSTRIDE + lm] = f2tf(rw[c].y);
                Wa[(kr + 2) * GSTRIDE + lm] = f2tf(rw[c].z);
                Wa[(kr + 3) * GSTRIDE + lm] = f2tf(rw[c].w);
            }
            __syncthreads();
        }
    }

    #pragma unroll
    for (int i = 0; i < 2; i++) {
        int r0 = rowBase + wm * 32 + i * 16 + g;
        #pragma unroll
        for (int j = 0; j < 8; j++) {
            int n = colBase + wn * 64 + j * 8 + 2 * t;
            size_t i0 = (size_t)r0 * N + n;
            size_t i1 = (size_t)(r0 + 8) * N + n;
            if (EPI == 0) {
                *(float2*)&Y[i0] = make_float2(acc[i][j][0], acc[i][j][1]);
                *(float2*)&Y[i1] = make_float2(acc[i][j][2], acc[i][j][3]);
            } else if (EPI == 1) {
                float2 y0 = *(float2*)&Y[i0];
                float2 y1 = *(float2*)&Y[i1];
                y0.x += acc[i][j][0]; y0.y += acc[i][j][1];
                y1.x += acc[i][j][2]; y1.y += acc[i][j][3];
                *(float2*)&Y[i0] = y0;
                *(float2*)&Y[i1] = y1;
            } else {
                *(float2*)&Y[i0] = make_float2(gelu_exact(acc[i][j][0]),
                                               gelu_exact(acc[i][j][1]));
                *(float2*)&Y[i1] = make_float2(gelu_exact(acc[i][j][2]),
                                               gelu_exact(acc[i][j][3]));
            }
        }
    }
}

// ---------------------------------------------------------------------------
// Flash attention, balanced pairing: block qp handles q-tiles qp and 31-qp.
// Uniform 33 k-tiles of work per block. 256 threads, fp32.
// ---------------------------------------------------------------------------
__global__ __launch_bounds__(256)
void fattn_kernel(const float* __restrict__ qkv,
                  float* __restrict__ out) {
    int qp = blockIdx.x;       // 0..15
    int h  = blockIdx.y;
    int b  = blockIdx.z;
    int tid = threadIdx.x;
    int tx = tid & 15;
    int ty = tid >> 4;

    __shared__ float Qs[64][64];
    __shared__ float KPs[64][64];
    __shared__ float Vs[64][64];

    int lq = tid & 63;
    int dg = (tid >> 6) * 16;

    #pragma unroll 1
    for (int ph = 0; ph < 2; ph++) {
        int qt = ph ? (NQT - 1 - qp) : qp;

        // Load Q tile (transposed)
        {
            const float* qb = qkv + ((size_t)(b * SEQ_T + qt * 64 + lq)) * (3 * D_MODEL)
                            + h * D_HEAD;
            #pragma unroll
            for (int it = 0; it < 4; it++) {
                float4 v = *(const float4*)(qb + dg + it * 4);
                Qs[dg + it * 4 + 0][lq] = v.x;
                Qs[dg + it * 4 + 1][lq] = v.y;
                Qs[dg + it * 4 + 2][lq] = v.z;
                Qs[dg + it * 4 + 3][lq] = v.w;
            }
        }

        float accO[4][4];
        #pragma unroll
        for (int i = 0; i < 4; i++)
            #pragma unroll
            for (int j = 0; j < 4; j++) accO[i][j] = 0.0f;
        float m_i[4] = {-1e30f, -1e30f, -1e30f, -1e30f};
        float l_i[4] = {0.0f, 0.0f, 0.0f, 0.0f};

        __syncthreads();

        for (int kt = 0; kt <= qt; kt++) {
            {
                const float* kb = qkv + ((size_t)(b * SEQ_T + kt * 64 + lq)) * (3 * D_MODEL)
                                + D_MODEL + h * D_HEAD;
                #pragma unroll
                for (int it = 0; it < 4; it++) {
                    float4 v = *(const float4*)(kb + dg + it * 4);
                    KPs[dg + it * 4 + 0][lq] = v.x;
                    KPs[dg + it * 4 + 1][lq] = v.y;
                    KPs[dg + it * 4 + 2][lq] = v.z;
                    KPs[dg + it * 4 + 3][lq] = v.w;
                }
                #pragma unroll
                for (int it = 0; it < 4; it++) {
                    int f = it * 256 + tid;
                    int kk = f >> 4;
                    int d4 = (f & 15) * 4;
                    const float* vb = qkv + ((size_t)(b * SEQ_T + kt * 64 + kk)) * (3 * D_MODEL)
                                    + 2 * D_MODEL + h * D_HEAD + d4;
                    float4 v = *(const float4*)vb;
                    *(float4*)&Vs[kk][d4] = v;
                }
            }
            __syncthreads();

            float s[4][4];
            #pragma unroll
            for (int i = 0; i < 4; i++)
                #pragma unroll
                for (int j = 0; j < 4; j++) s[i][j] = 0.0f;

            #pragma unroll 8
            for (int d = 0; d < 64; d++) {
                float4 qa = *(const float4*)&Qs[d][ty * 4];
                float4 ka = *(const float4*)&KPs[d][tx * 4];
                float a[4] = {qa.x, qa.y, qa.z, qa.w};
                float kv[4] = {ka.x, ka.y, ka.z, ka.w};
                #pragma unroll
                for (int i = 0; i < 4; i++)
                    #pragma unroll
                    for (int j = 0; j < 4; j++)
                        s[i][j] += a[i] * kv[j];
            }

            #pragma unroll
            for (int i = 0; i < 4; i++)
                #pragma unroll
                for (int j = 0; j < 4; j++) {
                    s[i][j] *= 0.125f;
                    if (kt == qt) {
                        int gq = ty * 4 + i;
                        int gk = tx * 4 + j;
                        if (gk > gq) s[i][j] = -1e30f;
                    }
                }

            float p[4][4];
            #pragma unroll
            for (int i = 0; i < 4; i++) {
                float rmax = fmaxf(fmaxf(s[i][0], s[i][1]), fmaxf(s[i][2], s[i][3]));
                #pragma unroll
                for (int off = 1; off < 16; off <<= 1)
                    rmax = fmaxf(rmax, __shfl_xor_sync(0xffffffffu, rmax, off));
                float m_new = fmaxf(m_i[i], rmax);
                float scale = __expf(m_i[i] - m_new);
                float rs = 0.0f;
                #pragma unroll
                for (int j = 0; j < 4; j++) {
                    p[i][j] = __expf(s[i][j] - m_new);
                    rs += p[i][j];
                }
                #pragma unroll
                for (int off = 1; off < 16; off <<= 1)
                    rs += __shfl_xor_sync(0xffffffffu, rs, off);
                l_i[i] = l_i[i] * scale + rs;
                m_i[i] = m_new;
                #pragma unroll
                for (int j = 0; j < 4; j++) accO[i][j] *= scale;
            }

            __syncthreads();

            #pragma unroll
            for (int i = 0; i < 4; i++)
                *(float4*)&KPs[ty * 4 + i][tx * 4] =
                    make_float4(p[i][0], p[i][1], p[i][2], p[i][3]);
            __syncthreads();

            #pragma unroll 4
            for (int k = 0; k < 64; k++) {
                float4 vv = *(const float4*)&Vs[k][tx * 4];
                float v4[4] = {vv.x, vv.y, vv.z, vv.w};
                #pragma unroll
                for (int i = 0; i < 4; i++) {
                    float pk = KPs[ty * 4 + i][k];
                    #pragma unroll
                    for (int j = 0; j < 4; j++)
                        accO[i][j] += pk * v4[j];
                }
            }
            __syncthreads();
        }

        // epilogue for this q-tile
        #pragma unroll
        for (int i = 0; i < 4; i++) {
            float inv = 1.0f / l_i[i];
            size_t row = (size_t)(b * SEQ_T + qt * 64 + ty * 4 + i);
            float* orow = out + row * D_MODEL + h * D_HEAD + tx * 4;
            orow[0] = accO[i][0] * inv;
            orow[1] = accO[i][1] * inv;
            orow[2] = accO[i][2] * inv;
            orow[3] = accO[i][3] * inv;
        }
    }
}

// ---------------------------------------------------------------------------
// Host launcher
// ---------------------------------------------------------------------------
extern "C" void kernel_launch(void* const* d_in, const int* in_sizes, int n_in,
                              void* d_out, int out_size) {
    const int*   x       = (const int*)  d_in[0];
    const float* tok_emb = (const float*)d_in[1];
    const float* pos_emb = (const float*)d_in[2];
    const float* qkv_w   = (const float*)d_in[3];
    const float* proj_w  = (const float*)d_in[4];
    const float* ln1_w   = (const float*)d_in[5];
    const float* ln1_b   = (const float*)d_in[6];
    const float* ln2_w   = (const float*)d_in[7];
    const float* ln2_b   = (const float*)d_in[8];
    const float* fc1_w   = (const float*)d_in[9];
    const float* fc2_w   = (const float*)d_in[10];
    const float* lnf_w   = (const float*)d_in[11];
    const float* lnf_b   = (const float*)d_in[12];
    const float* head_w  = (const float*)d_in[13];
    float* out = (float*)d_out;

    float *ph, *pln, *pqkv, *pattn, *pff;
    cudaGetSymbolAddress((void**)&ph,    g_h);
    cudaGetSymbolAddress((void**)&pln,   g_ln);
    cudaGetSymbolAddress((void**)&pqkv,  g_qkv);
    cudaGetSymbolAddress((void**)&pattn, g_attn);
    cudaGetSymbolAddress((void**)&pff,   g_ff);

    cudaFuncSetAttribute(gemm_tf32_kernel<0>,
                         cudaFuncAttributeMaxDynamicSharedMemorySize, GEMM_SMEM);
    cudaFuncSetAttribute(gemm_tf32_kernel<1>,
                         cudaFuncAttributeMaxDynamicSharedMemorySize, GEMM_SMEM);
    cudaFuncSetAttribute(gemm_tf32_kernel<2>,
                         cudaFuncAttributeMaxDynamicSharedMemorySize, GEMM_SMEM);

    embed_kernel<<<(MROWS * D_MODEL + 255) / 256, 256>>>(x, tok_emb, pos_emb, ph);

    for (int l = 0; l < DEPTH; l++) {
        const float* qw  = qkv_w  + (size_t)l * 3 * D_MODEL * D_MODEL;
        const float* pw  = proj_w + (size_t)l * D_MODEL * D_MODEL;
        const float* f1w = fc1_w  + (size_t)l * D_FF * D_MODEL;
        const float* f2w = fc2_w  + (size_t)l * D_MODEL * D_FF;

        ln_kernel<<<MROWS, 256>>>(ph, ln1_w + l * D_MODEL, ln1_b + l * D_MODEL, pln);

        gemm_tf32_kernel<0><<<dim3(3 * D_MODEL / 128, MROWS / 128), 256, GEMM_SMEM>>>(
            pln, qw, pqkv, MROWS, 3 * D_MODEL, D_MODEL);

        fattn_kernel<<<dim3(NQT / 2, N_HEADS, BB), 256>>>(pqkv, pattn);

        gemm_tf32_kernel<1><<<dim3(D_MODEL / 128, MROWS / 128), 256, GEMM_SMEM>>>(
            pattn, pw, ph, MROWS, D_MODEL, D_MODEL);

        ln_kernel<<<MROWS, 256>>>(ph, ln2_w + l * D_MODEL, ln2_b + l * D_MODEL, pln);

        gemm_tf32_kernel<2><<<dim3(D_FF / 128, MROWS / 128), 256, GEMM_SMEM>>>(
            pln, f1w, pff, MROWS, D_FF, D_MODEL);

        gemm_tf32_kernel<1><<<dim3(D_MODEL / 128, MROWS / 128), 256, GEMM_SMEM>>>(
            pff, f2w, ph, MROWS, D_MODEL, D_FF);
    }

    ln_kernel<<<MROWS, 256>>>(ph, lnf_w, lnf_b, pln);
    gemm_tf32_kernel<0><<<dim3(VOCAB / 128, MROWS / 128), 256, GEMM_SMEM>>>(
        pln, head_w, out, MROWS, VOCAB, D_MODEL);

    (void)in_sizes; (void)n_in; (void)out_size;
}